// round 2
// baseline (speedup 1.0000x reference)
#include <cuda_runtime.h>

#define BB 16
#define NN 8192
#define SS 1024
#define KK 32
#define NROWS (BB*SS*KK)        // 524288
#define NINV  (1.0f/524288.0f)  // exact power of two
#define R2 0.04f

// ---------------- scratch (device globals: no allocation allowed) ----------------
__device__ int    g_ball[NROWS];
__device__ float4 g_xyzp[BB*NN];
__device__ float4 g_pts4[BB*NN];
__device__ float  g_x[(size_t)NROWS*6];
__device__ float  g_z2[(size_t)NROWS*64];
__device__ float  g_z3[(size_t)NROWS*128];
__device__ float  g_stats0[27];
__device__ float  g_sum2[64],  g_sumsq2[64];
__device__ float  g_sum3[128], g_sumsq3[128];
__device__ float  g_scale1[64], g_shift1[64];
__device__ float  g_scale2[64], g_shift2[64];
__device__ float  g_scale3[128], g_shift3[128];

// ---------------- zero stats (graph replays must re-zero) ----------------
__global__ void zero_kernel() {
    int t = threadIdx.x;
    if (t < 27)  g_stats0[t] = 0.f;
    if (t < 64)  { g_sum2[t] = 0.f; g_sumsq2[t] = 0.f; }
    if (t < 128) { g_sum3[t] = 0.f; g_sumsq3[t] = 0.f; }
}

// ---------------- prep: pack xyz (+|p|^2) and points into float4 ----------------
__global__ void prep_kernel(const float* __restrict__ xyz, const float* __restrict__ pts) {
    int i = blockIdx.x * blockDim.x + threadIdx.x;
    if (i < BB*NN) {
        float x = xyz[3*i], y = xyz[3*i+1], z = xyz[3*i+2];
        g_xyzp[i] = make_float4(x, y, z, fmaf(x,x,fmaf(y,y,z*z)));
        g_pts4[i] = make_float4(pts[3*i], pts[3*i+1], pts[3*i+2], 0.f);
    }
}

// ---------------- FPS: one block per batch, points resident in registers ----------------
__global__ __launch_bounds__(512) void fps_kernel(const float* __restrict__ xyz,
                                                  float* __restrict__ new_xyz) {
    const int b = blockIdx.x;
    const float* base = xyz + (size_t)b * NN * 3;
    const int t = threadIdx.x;

    float px[16], py[16], pz[16], dist[16];
#pragma unroll
    for (int j = 0; j < 16; j++) {
        int i = j*512 + t;
        px[j] = base[3*i]; py[j] = base[3*i+1]; pz[j] = base[3*i+2];
        dist[j] = 1e10f;
    }

    __shared__ float s_c[3];
    __shared__ float s_val[16];
    __shared__ int   s_idx[16];
    if (t == 0) { s_c[0] = base[0]; s_c[1] = base[1]; s_c[2] = base[2]; }
    __syncthreads();

    float* out = new_xyz + (size_t)b * SS * 3;
    for (int it = 0; it < SS; it++) {
        float cx = s_c[0], cy = s_c[1], cz = s_c[2];
        if (t == 0) { out[3*it] = cx; out[3*it+1] = cy; out[3*it+2] = cz; }

        float bv = -1.f; int bi = 0;
#pragma unroll
        for (int j = 0; j < 16; j++) {
            float dx = px[j] - cx, dy = py[j] - cy, dz = pz[j] - cz;
            float d  = fmaf(dx,dx, fmaf(dy,dy, dz*dz));
            float nd = fminf(dist[j], d);
            dist[j] = nd;
            if (nd > bv) { bv = nd; bi = j*512 + t; }   // ascending index within thread
        }
        // warp argmax, lower index wins ties (match jnp.argmax first-occurrence)
#pragma unroll
        for (int o = 16; o > 0; o >>= 1) {
            float ov = __shfl_down_sync(0xffffffffu, bv, o);
            int   oi = __shfl_down_sync(0xffffffffu, bi, o);
            if (ov > bv || (ov == bv && oi < bi)) { bv = ov; bi = oi; }
        }
        if ((t & 31) == 0) { s_val[t>>5] = bv; s_idx[t>>5] = bi; }
        __syncthreads();
        if (t < 32) {
            float v2 = (t < 16) ? s_val[t] : -1.f;
            int   i2 = (t < 16) ? s_idx[t] : 0;
#pragma unroll
            for (int o = 8; o > 0; o >>= 1) {
                float ov = __shfl_down_sync(0xffffffffu, v2, o);
                int   oi = __shfl_down_sync(0xffffffffu, i2, o);
                if (ov > v2 || (ov == v2 && oi < i2)) { v2 = ov; i2 = oi; }
            }
            if (t == 0) {
                s_c[0] = base[3*i2]; s_c[1] = base[3*i2+1]; s_c[2] = base[3*i2+2];
            }
        }
        __syncthreads();
    }
}

// ---------------- ball query: one warp per centroid, ordered first-32 collection ----------------
__global__ __launch_bounds__(256) void ball_kernel(const float* __restrict__ new_xyz) {
    int w    = (blockIdx.x * 256 + threadIdx.x) >> 5;  // global centroid id (b*S+s)
    int lane = threadIdx.x & 31;
    int b    = w >> 10;
    const float4* xp = g_xyzp + b * NN;
    float cx = new_xyz[3*w], cy = new_xyz[3*w+1], cz = new_xyz[3*w+2];
    float ss = fmaf(cx,cx, fmaf(cy,cy, cz*cz));
    int* outp = g_ball + w * KK;

    int count = 0, first = 0;
    for (int base = 0; base < NN; base += 32) {
        float4 p = xp[base + lane];
        float dot = fmaf(cx,p.x, fmaf(cy,p.y, cz*p.z));
        float sq  = fmaf(-2.f, dot, ss) + p.w;     // matches (|s|^2 - 2 s.p) + |p|^2
        bool hit  = !(sq > R2);
        unsigned m = __ballot_sync(0xffffffffu, hit);
        if (count == 0 && m) first = base + __ffs(m) - 1;
        int pos = count + __popc(m & ((1u << lane) - 1u));
        if (hit && pos < KK) outp[pos] = base + lane;
        count += __popc(m);
        if (count >= KK) break;
    }
    if (count < KK && lane >= count && lane < KK) outp[lane] = first;
}

// ---------------- pass A: gather features, store x, accumulate 6-vec mean + 21 Gram ----------------
__global__ __launch_bounds__(256) void passA_kernel(const float* __restrict__ new_xyz) {
    int gt = blockIdx.x * 256 + threadIdx.x;   // 65536 threads, 8 rows each
    float acc[27];
#pragma unroll
    for (int q = 0; q < 27; q++) acc[q] = 0.f;

    for (int i = 0; i < 8; i++) {
        int row = i * 65536 + gt;
        int idx = g_ball[row];
        int b   = row >> 15;
        int bs  = row >> 5;
        float4 p = g_xyzp[b*NN + idx];
        float4 q = g_pts4[b*NN + idx];
        float f[6];
        f[0] = p.x - new_xyz[3*bs];
        f[1] = p.y - new_xyz[3*bs+1];
        f[2] = p.z - new_xyz[3*bs+2];
        f[3] = q.x; f[4] = q.y; f[5] = q.z;
        float* xr = g_x + (size_t)row * 6;
#pragma unroll
        for (int c = 0; c < 6; c++) xr[c] = f[c];
#pragma unroll
        for (int c = 0; c < 6; c++) acc[c] += f[c];
        int pidx = 6;
#pragma unroll
        for (int a = 0; a < 6; a++)
#pragma unroll
            for (int c = a; c < 6; c++) acc[pidx++] = fmaf(f[a], f[c], acc[pidx]);
    }
#pragma unroll
    for (int q = 0; q < 27; q++) {
        float v = acc[q];
#pragma unroll
        for (int o = 16; o > 0; o >>= 1) v += __shfl_down_sync(0xffffffffu, v, o);
        if ((threadIdx.x & 31) == 0) atomicAdd(&g_stats0[q], v);
    }
}

// ---------------- params1: layer-1 BN stats from Gram ----------------
__global__ void params1_kernel(const float* __restrict__ w1, const float* __restrict__ b1,
                               const float* __restrict__ g1, const float* __restrict__ be1) {
    __shared__ float mu[6], C2[6][6];
    int t = threadIdx.x;
    if (t < 6) mu[t] = g_stats0[t] * NINV;
    if (t < 36) {
        int i = t / 6, j = t % 6;
        int a = i < j ? i : j, c = i < j ? j : i;
        int pos = 6 + 6*a - (a*(a-1))/2 + (c - a);
        C2[i][j] = g_stats0[pos] * NINV;
    }
    __syncthreads();
    if (t < 64) {
        float lin = 0.f;
#pragma unroll
        for (int c = 0; c < 6; c++) lin += w1[t*6+c] * mu[c];
        float m = lin + b1[t];
        float qv = 0.f;
#pragma unroll
        for (int i = 0; i < 6; i++)
#pragma unroll
            for (int j = 0; j < 6; j++) qv += w1[t*6+i] * w1[t*6+j] * C2[i][j];
        float Ez2 = qv + 2.f * b1[t] * lin + b1[t]*b1[t];
        float var = Ez2 - m*m;
        float sc  = g1[t] * rsqrtf(var + 1e-5f);
        g_scale1[t] = sc;
        g_shift1[t] = be1[t] - m * sc;
    }
}

// ---------------- pass B: layer1 (affine-folded) + layer2 GEMM + z2 stats ----------------
__global__ __launch_bounds__(256) void passB_kernel(const float* __restrict__ w1, const float* __restrict__ b1,
                                                    const float* __restrict__ w2, const float* __restrict__ b2) {
    __shared__ float a1[64][65];
    __shared__ __align__(16) float w2s[64][64];   // [c][o]
    __shared__ float w1s[64][6], b1s[64], sc1[64], sh1[64], b2s[64];
    __shared__ float psum[16][64], psq[16][64];
    int tid = threadIdx.x;

    for (int i = tid; i < 4096; i += 256) { int o = i >> 6, c = i & 63; w2s[c][o] = w2[i]; }
    for (int i = tid; i < 384; i += 256) w1s[i/6][i%6] = w1[i];
    if (tid < 64) { b1s[tid] = b1[tid]; sc1[tid] = g_scale1[tid]; sh1[tid] = g_shift1[tid]; b2s[tid] = b2[tid]; }
    __syncthreads();

    int rowBase = blockIdx.x * 64;
    {   // stage 1: a1 = relu(affine1(W1 x + b1))
        int r = tid >> 2, c0 = (tid & 3) * 16;
        const float* xr = g_x + (size_t)(rowBase + r) * 6;
        float x0=xr[0], x1=xr[1], x2=xr[2], x3=xr[3], x4=xr[4], x5=xr[5];
#pragma unroll
        for (int c = 0; c < 16; c++) {
            int o = c0 + c;
            float z = b1s[o];
            z = fmaf(w1s[o][0],x0, z); z = fmaf(w1s[o][1],x1, z); z = fmaf(w1s[o][2],x2, z);
            z = fmaf(w1s[o][3],x3, z); z = fmaf(w1s[o][4],x4, z); z = fmaf(w1s[o][5],x5, z);
            a1[r][o] = fmaxf(fmaf(z, sc1[o], sh1[o]), 0.f);
        }
    }
    __syncthreads();

    int tx = tid & 15, ty = tid >> 4;
    float acc[4][4];
#pragma unroll
    for (int i = 0; i < 4; i++)
#pragma unroll
        for (int j = 0; j < 4; j++) acc[i][j] = b2s[tx*4 + j];

#pragma unroll 4
    for (int k = 0; k < 64; k++) {
        float av[4];
#pragma unroll
        for (int i = 0; i < 4; i++) av[i] = a1[ty*4 + i][k];
        float4 wv = *(const float4*)&w2s[k][tx*4];
#pragma unroll
        for (int i = 0; i < 4; i++) {
            acc[i][0] = fmaf(av[i], wv.x, acc[i][0]);
            acc[i][1] = fmaf(av[i], wv.y, acc[i][1]);
            acc[i][2] = fmaf(av[i], wv.z, acc[i][2]);
            acc[i][3] = fmaf(av[i], wv.w, acc[i][3]);
        }
    }
    float cs[4] = {0,0,0,0}, cq[4] = {0,0,0,0};
#pragma unroll
    for (int i = 0; i < 4; i++) {
        float4 v = make_float4(acc[i][0], acc[i][1], acc[i][2], acc[i][3]);
        *(float4*)&g_z2[(size_t)(rowBase + ty*4 + i) * 64 + tx*4] = v;
        cs[0]+=v.x; cs[1]+=v.y; cs[2]+=v.z; cs[3]+=v.w;
        cq[0]=fmaf(v.x,v.x,cq[0]); cq[1]=fmaf(v.y,v.y,cq[1]); cq[2]=fmaf(v.z,v.z,cq[2]); cq[3]=fmaf(v.w,v.w,cq[3]);
    }
#pragma unroll
    for (int j = 0; j < 4; j++) { psum[ty][tx*4+j] = cs[j]; psq[ty][tx*4+j] = cq[j]; }
    __syncthreads();
    if (tid < 64) {
        float s = 0.f, s2 = 0.f;
#pragma unroll
        for (int y = 0; y < 16; y++) { s += psum[y][tid]; s2 += psq[y][tid]; }
        atomicAdd(&g_sum2[tid], s);
        atomicAdd(&g_sumsq2[tid], s2);
    }
}

__global__ void params2_kernel(const float* __restrict__ g2, const float* __restrict__ be2) {
    int t = threadIdx.x;
    if (t < 64) {
        float m = g_sum2[t] * NINV;
        float var = g_sumsq2[t] * NINV - m*m;
        float sc = g2[t] * rsqrtf(var + 1e-5f);
        g_scale2[t] = sc; g_shift2[t] = be2[t] - m * sc;
    }
}

// ---------------- pass C: layer3 GEMM (64-col halves) + z3 stats ----------------
__global__ __launch_bounds__(256) void passC_kernel(const float* __restrict__ w3, const float* __restrict__ b3) {
    __shared__ float a2[64][65];
    __shared__ __align__(16) float w3s[64][64];   // [c][o-in-half]
    __shared__ float sc2[64], sh2[64], b3s[64];
    __shared__ float psum[16][64], psq[16][64];
    int tid = threadIdx.x;
    int colBase = blockIdx.y * 64;

    for (int i = tid; i < 4096; i += 256) {
        int o = i >> 6, c = i & 63;
        w3s[c][o] = w3[(size_t)(colBase + o) * 64 + c];
    }
    if (tid < 64) { sc2[tid] = g_scale2[tid]; sh2[tid] = g_shift2[tid]; b3s[tid] = b3[colBase + tid]; }
    __syncthreads();

    int rowBase = blockIdx.x * 64;
    {   // stage 1: a2 = relu(affine2(z2))
        int r = tid >> 2, c0 = (tid & 3) * 16;
        const float* zr = g_z2 + (size_t)(rowBase + r) * 64;
#pragma unroll
        for (int c = 0; c < 16; c++) {
            int o = c0 + c;
            a2[r][o] = fmaxf(fmaf(zr[o], sc2[o], sh2[o]), 0.f);
        }
    }
    __syncthreads();

    int tx = tid & 15, ty = tid >> 4;
    float acc[4][4];
#pragma unroll
    for (int i = 0; i < 4; i++)
#pragma unroll
        for (int j = 0; j < 4; j++) acc[i][j] = b3s[tx*4 + j];

#pragma unroll 4
    for (int k = 0; k < 64; k++) {
        float av[4];
#pragma unroll
        for (int i = 0; i < 4; i++) av[i] = a2[ty*4 + i][k];
        float4 wv = *(const float4*)&w3s[k][tx*4];
#pragma unroll
        for (int i = 0; i < 4; i++) {
            acc[i][0] = fmaf(av[i], wv.x, acc[i][0]);
            acc[i][1] = fmaf(av[i], wv.y, acc[i][1]);
            acc[i][2] = fmaf(av[i], wv.z, acc[i][2]);
            acc[i][3] = fmaf(av[i], wv.w, acc[i][3]);
        }
    }
    float cs[4] = {0,0,0,0}, cq[4] = {0,0,0,0};
#pragma unroll
    for (int i = 0; i < 4; i++) {
        float4 v = make_float4(acc[i][0], acc[i][1], acc[i][2], acc[i][3]);
        *(float4*)&g_z3[(size_t)(rowBase + ty*4 + i) * 128 + colBase + tx*4] = v;
        cs[0]+=v.x; cs[1]+=v.y; cs[2]+=v.z; cs[3]+=v.w;
        cq[0]=fmaf(v.x,v.x,cq[0]); cq[1]=fmaf(v.y,v.y,cq[1]); cq[2]=fmaf(v.z,v.z,cq[2]); cq[3]=fmaf(v.w,v.w,cq[3]);
    }
#pragma unroll
    for (int j = 0; j < 4; j++) { psum[ty][tx*4+j] = cs[j]; psq[ty][tx*4+j] = cq[j]; }
    __syncthreads();
    if (tid < 64) {
        float s = 0.f, s2 = 0.f;
#pragma unroll
        for (int y = 0; y < 16; y++) { s += psum[y][tid]; s2 += psq[y][tid]; }
        atomicAdd(&g_sum3[colBase + tid], s);
        atomicAdd(&g_sumsq3[colBase + tid], s2);
    }
}

__global__ void params3_kernel(const float* __restrict__ g3, const float* __restrict__ be3) {
    int t = threadIdx.x;
    if (t < 128) {
        float m = g_sum3[t] * NINV;
        float var = g_sumsq3[t] * NINV - m*m;
        float sc = g3[t] * rsqrtf(var + 1e-5f);
        g_scale3[t] = sc; g_shift3[t] = be3[t] - m * sc;
    }
}

// ---------------- pass D: affine3 + max over K + relu ----------------
__global__ __launch_bounds__(256) void passD_kernel(float* __restrict__ out_pts) {
    int w    = (blockIdx.x * 256 + threadIdx.x) >> 5;   // group (b*S+s)
    int lane = threadIdx.x & 31;
    int c0   = lane * 4;
    float sc[4], sh[4];
#pragma unroll
    for (int j = 0; j < 4; j++) { sc[j] = g_scale3[c0+j]; sh[j] = g_shift3[c0+j]; }
    float m0 = -1e30f, m1 = -1e30f, m2 = -1e30f, m3 = -1e30f;
    const float* zr = g_z3 + (size_t)w * KK * 128;
#pragma unroll 4
    for (int r = 0; r < KK; r++) {
        float4 v = *(const float4*)&zr[r*128 + c0];
        m0 = fmaxf(m0, fmaf(v.x, sc[0], sh[0]));
        m1 = fmaxf(m1, fmaf(v.y, sc[1], sh[1]));
        m2 = fmaxf(m2, fmaf(v.z, sc[2], sh[2]));
        m3 = fmaxf(m3, fmaf(v.w, sc[3], sh[3]));
    }
    float4 o = make_float4(fmaxf(m0,0.f), fmaxf(m1,0.f), fmaxf(m2,0.f), fmaxf(m3,0.f));
    *(float4*)&out_pts[(size_t)w * 128 + c0] = o;
}

// ---------------- launch ----------------
extern "C" void kernel_launch(void* const* d_in, const int* in_sizes, int n_in,
                              void* d_out, int out_size) {
    const float* xyz = (const float*)d_in[0];
    const float* pts = (const float*)d_in[1];
    const float* w1  = (const float*)d_in[2];
    const float* b1  = (const float*)d_in[3];
    const float* g1  = (const float*)d_in[4];
    const float* be1 = (const float*)d_in[5];
    const float* w2  = (const float*)d_in[6];
    const float* b2  = (const float*)d_in[7];
    const float* g2  = (const float*)d_in[8];
    const float* be2 = (const float*)d_in[9];
    const float* w3  = (const float*)d_in[10];
    const float* b3  = (const float*)d_in[11];
    const float* g3  = (const float*)d_in[12];
    const float* be3 = (const float*)d_in[13];

    float* out      = (float*)d_out;
    float* new_xyz  = out;                 // 16*1024*3 = 49152 floats
    float* new_pts  = out + 49152;         // 16*1024*128 floats

    zero_kernel<<<1, 256>>>();
    prep_kernel<<<512, 256>>>(xyz, pts);
    fps_kernel<<<BB, 512>>>(xyz, new_xyz);
    ball_kernel<<<2048, 256>>>(new_xyz);
    passA_kernel<<<256, 256>>>(new_xyz);
    params1_kernel<<<1, 64>>>(w1, b1, g1, be1);
    passB_kernel<<<8192, 256>>>(w1, b1, w2, b2);
    params2_kernel<<<1, 64>>>(g2, be2);
    passC_kernel<<<dim3(8192, 2), 256>>>(w3, b3);
    params3_kernel<<<1, 128>>>(g3, be3);
    passD_kernel<<<2048, 256>>>(new_pts);
}

// round 4
// speedup vs baseline: 1.1222x; 1.1222x over previous
#include <cuda_runtime.h>

#define BB 16
#define NN 8192
#define SS 1024
#define KK 32
#define NROWS (BB*SS*KK)        // 524288
#define NINV  (1.0f/524288.0f)  // exact power of two
#define R2 0.04f

typedef unsigned long long ull;

// ---------------- f32x2 packed helpers (Blackwell) ----------------
__device__ __forceinline__ ull pack2(float lo, float hi) {
    ull r;
    asm("mov.b64 %0, {%1, %2};" : "=l"(r) : "r"(__float_as_uint(lo)), "r"(__float_as_uint(hi)));
    return r;
}
__device__ __forceinline__ void unpack2(ull v, float& lo, float& hi) {
    unsigned a, b;
    asm("mov.b64 {%0, %1}, %2;" : "=r"(a), "=r"(b) : "l"(v));
    lo = __uint_as_float(a); hi = __uint_as_float(b);
}
__device__ __forceinline__ ull add2(ull a, ull b) {
    ull d; asm("add.rn.f32x2 %0, %1, %2;" : "=l"(d) : "l"(a), "l"(b)); return d;
}
__device__ __forceinline__ ull mul2(ull a, ull b) {
    ull d; asm("mul.rn.f32x2 %0, %1, %2;" : "=l"(d) : "l"(a), "l"(b)); return d;
}
__device__ __forceinline__ ull fma2(ull a, ull b, ull c) {
    ull d; asm("fma.rn.f32x2 %0, %1, %2, %3;" : "=l"(d) : "l"(a), "l"(b), "l"(c)); return d;
}

// ---------------- scratch (device globals: no allocation allowed) ----------------
__device__ int    g_ball[NROWS];
__device__ float4 g_xyzp[BB*NN];
__device__ float4 g_pts4[BB*NN];
__device__ float  g_x[(size_t)NROWS*6];
__device__ float  g_z2[(size_t)NROWS*64];
__device__ float  g_max3[BB*SS*128];
__device__ float  g_min3[BB*SS*128];
__device__ float  g_stats0[27];
__device__ float  g_sum2[64],  g_sumsq2[64];
__device__ float  g_sum3[128], g_sumsq3[128];
__device__ float  g_scale1[64], g_shift1[64];
__device__ float  g_scale2[64], g_shift2[64];
__device__ float  g_scale3[128], g_shift3[128];

// ---------------- zero stats (graph replays must re-zero) ----------------
__global__ void zero_kernel() {
    int t = threadIdx.x;
    if (t < 27)  g_stats0[t] = 0.f;
    if (t < 64)  { g_sum2[t] = 0.f; g_sumsq2[t] = 0.f; }
    if (t < 128) { g_sum3[t] = 0.f; g_sumsq3[t] = 0.f; }
}

// ---------------- prep: pack xyz (+|p|^2) and points into float4 ----------------
__global__ void prep_kernel(const float* __restrict__ xyz, const float* __restrict__ pts) {
    int i = blockIdx.x * blockDim.x + threadIdx.x;
    if (i < BB*NN) {
        float x = xyz[3*i], y = xyz[3*i+1], z = xyz[3*i+2];
        g_xyzp[i] = make_float4(x, y, z, fmaf(x,x,fmaf(y,y,z*z)));
        g_pts4[i] = make_float4(pts[3*i], pts[3*i+1], pts[3*i+2], 0.f);
    }
}

// ---------------- FPS: one block per batch, points packed f32x2 in registers ----------------
__global__ __launch_bounds__(512) void fps_kernel(const float* __restrict__ xyz,
                                                  float* __restrict__ new_xyz) {
    const int b = blockIdx.x;
    const float* base = xyz + (size_t)b * NN * 3;
    const int t = threadIdx.x;

    ull px2[8], py2[8], pz2[8];
    float dist[16];
#pragma unroll
    for (int p = 0; p < 8; p++) {
        int i0 = (2*p)*512 + t, i1 = i0 + 512;
        px2[p] = pack2(base[3*i0],   base[3*i1]);
        py2[p] = pack2(base[3*i0+1], base[3*i1+1]);
        pz2[p] = pack2(base[3*i0+2], base[3*i1+2]);
        dist[2*p] = 1e10f; dist[2*p+1] = 1e10f;
    }

    __shared__ float s_c[3];
    __shared__ float s_val[16];
    __shared__ int   s_idx[16];
    if (t == 0) { s_c[0] = base[0]; s_c[1] = base[1]; s_c[2] = base[2]; }
    __syncthreads();

    float* out = new_xyz + (size_t)b * SS * 3;
    for (int it = 0; it < SS; it++) {
        float cx = s_c[0], cy = s_c[1], cz = s_c[2];
        if (t == 0) { out[3*it] = cx; out[3*it+1] = cy; out[3*it+2] = cz; }
        ull nx2 = pack2(-cx, -cx), ny2 = pack2(-cy, -cy), nz2 = pack2(-cz, -cz);

        float bv = -1.f; int bi = 0;
#pragma unroll
        for (int p = 0; p < 8; p++) {
            ull dx = add2(px2[p], nx2);
            ull dy = add2(py2[p], ny2);
            ull dz = add2(pz2[p], nz2);
            ull d2 = fma2(dx, dx, fma2(dy, dy, mul2(dz, dz)));
            float d0, d1; unpack2(d2, d0, d1);
            float nd0 = fminf(dist[2*p], d0);   dist[2*p]   = nd0;
            if (nd0 > bv) { bv = nd0; bi = (2*p)*512 + t; }
            float nd1 = fminf(dist[2*p+1], d1); dist[2*p+1] = nd1;
            if (nd1 > bv) { bv = nd1; bi = (2*p+1)*512 + t; }
        }
        // warp argmax, lower index wins ties (match jnp.argmax first-occurrence)
#pragma unroll
        for (int o = 16; o > 0; o >>= 1) {
            float ov = __shfl_down_sync(0xffffffffu, bv, o);
            int   oi = __shfl_down_sync(0xffffffffu, bi, o);
            if (ov > bv || (ov == bv && oi < bi)) { bv = ov; bi = oi; }
        }
        if ((t & 31) == 0) { s_val[t>>5] = bv; s_idx[t>>5] = bi; }
        __syncthreads();
        if (t < 32) {
            float v2 = (t < 16) ? s_val[t] : -1.f;
            int   i2 = (t < 16) ? s_idx[t] : 0;
#pragma unroll
            for (int o = 8; o > 0; o >>= 1) {
                float ov = __shfl_down_sync(0xffffffffu, v2, o);
                int   oi = __shfl_down_sync(0xffffffffu, i2, o);
                if (ov > v2 || (ov == v2 && oi < i2)) { v2 = ov; i2 = oi; }
            }
            if (t == 0) {
                s_c[0] = base[3*i2]; s_c[1] = base[3*i2+1]; s_c[2] = base[3*i2+2];
            }
        }
        __syncthreads();
    }
}

// ---------------- ball query: one warp per centroid, pipelined (MLP=4) ----------------
__global__ __launch_bounds__(256) void ball_kernel(const float* __restrict__ new_xyz) {
    int w    = (blockIdx.x * 256 + threadIdx.x) >> 5;  // global centroid id (b*S+s)
    int lane = threadIdx.x & 31;
    int b    = w >> 10;
    const float4* xp = g_xyzp + b * NN;
    float cx = new_xyz[3*w], cy = new_xyz[3*w+1], cz = new_xyz[3*w+2];
    float ss = fmaf(cx,cx, fmaf(cy,cy, cz*cz));
    int* outp = g_ball + w * KK;

    int count = 0, first = 0;
    for (int base = 0; base < NN && count < KK; base += 128) {
        float4 p0 = xp[base      + lane];
        float4 p1 = xp[base + 32 + lane];
        float4 p2 = xp[base + 64 + lane];
        float4 p3 = xp[base + 96 + lane];
#define BQ_STEP(P, OFF) { \
        float dot = fmaf(cx,(P).x, fmaf(cy,(P).y, cz*(P).z)); \
        float sq  = fmaf(-2.f, dot, ss) + (P).w; \
        bool hit  = !(sq > R2); \
        unsigned m = __ballot_sync(0xffffffffu, hit); \
        if (count == 0 && m) first = base + (OFF) + __ffs(m) - 1; \
        int pos = count + __popc(m & ((1u << lane) - 1u)); \
        if (hit && pos < KK) outp[pos] = base + (OFF) + lane; \
        count += __popc(m); }
        BQ_STEP(p0, 0) BQ_STEP(p1, 32) BQ_STEP(p2, 64) BQ_STEP(p3, 96)
#undef BQ_STEP
    }
    if (count < KK && lane >= count && lane < KK) outp[lane] = first;
}

// ---------------- pass A: gather features, store x, accumulate 6-vec mean + 21 Gram ----------------
__global__ __launch_bounds__(256) void passA_kernel(const float* __restrict__ new_xyz) {
    int gt = blockIdx.x * 256 + threadIdx.x;   // 65536 threads, 8 rows each
    float acc[27];
#pragma unroll
    for (int q = 0; q < 27; q++) acc[q] = 0.f;

    for (int i = 0; i < 8; i++) {
        int row = i * 65536 + gt;
        int idx = g_ball[row];
        int b   = row >> 15;
        int bs  = row >> 5;
        float4 p = g_xyzp[b*NN + idx];
        float4 q = g_pts4[b*NN + idx];
        float f[6];
        f[0] = p.x - new_xyz[3*bs];
        f[1] = p.y - new_xyz[3*bs+1];
        f[2] = p.z - new_xyz[3*bs+2];
        f[3] = q.x; f[4] = q.y; f[5] = q.z;
        float* xr = g_x + (size_t)row * 6;
#pragma unroll
        for (int c = 0; c < 6; c++) xr[c] = f[c];
#pragma unroll
        for (int c = 0; c < 6; c++) acc[c] += f[c];
        int pidx = 6;
#pragma unroll
        for (int a = 0; a < 6; a++)
#pragma unroll
            for (int c = a; c < 6; c++) acc[pidx++] = fmaf(f[a], f[c], acc[pidx]);
    }
#pragma unroll
    for (int q = 0; q < 27; q++) {
        float v = acc[q];
#pragma unroll
        for (int o = 16; o > 0; o >>= 1) v += __shfl_down_sync(0xffffffffu, v, o);
        if ((threadIdx.x & 31) == 0) atomicAdd(&g_stats0[q], v);
    }
}

// ---------------- params1: layer-1 BN stats from Gram ----------------
__global__ void params1_kernel(const float* __restrict__ w1, const float* __restrict__ b1,
                               const float* __restrict__ g1, const float* __restrict__ be1) {
    __shared__ float mu[6], C2[6][6];
    int t = threadIdx.x;
    if (t < 6) mu[t] = g_stats0[t] * NINV;
    if (t < 36) {
        int i = t / 6, j = t % 6;
        int a = i < j ? i : j, c = i < j ? j : i;
        int pos = 6 + 6*a - (a*(a-1))/2 + (c - a);
        C2[i][j] = g_stats0[pos] * NINV;
    }
    __syncthreads();
    if (t < 64) {
        float lin = 0.f;
#pragma unroll
        for (int c = 0; c < 6; c++) lin += w1[t*6+c] * mu[c];
        float m = lin + b1[t];
        float qv = 0.f;
#pragma unroll
        for (int i = 0; i < 6; i++)
#pragma unroll
            for (int j = 0; j < 6; j++) qv += w1[t*6+i] * w1[t*6+j] * C2[i][j];
        float Ez2 = qv + 2.f * b1[t] * lin + b1[t]*b1[t];
        float var = Ez2 - m*m;
        float sc  = g1[t] * rsqrtf(var + 1e-5f);
        g_scale1[t] = sc;
        g_shift1[t] = be1[t] - m * sc;
    }
}

// ---------------- pass B: layer1 (affine-folded) + layer2 GEMM (f32x2) + z2 stats ----------------
__global__ __launch_bounds__(128) void passB_kernel(const float* __restrict__ w1, const float* __restrict__ b1,
                                                    const float* __restrict__ w2, const float* __restrict__ b2) {
    __shared__ __align__(16) float a1T[64][72];   // [k][row]
    __shared__ __align__(16) float w2s[64][64];   // [k][o]
    __shared__ float w1s[64][6], b1s[64], sc1[64], sh1[64], b2s[64];
    __shared__ float psum[8][64], psq[8][64];
    int tid = threadIdx.x;

    for (int i = tid; i < 4096; i += 128) { int o = i >> 6, c = i & 63; w2s[c][o] = w2[i]; }
    for (int i = tid; i < 384; i += 128) w1s[i/6][i%6] = w1[i];
    if (tid < 64) { b1s[tid] = b1[tid]; sc1[tid] = g_scale1[tid]; sh1[tid] = g_shift1[tid]; b2s[tid] = b2[tid]; }
    __syncthreads();

    int rowBase = blockIdx.x * 64;
    {   // stage 1: a1T[o][r] = relu(affine1(W1 x + b1)), transposed store
        int r = tid >> 1, o0 = (tid & 1) * 32;
        const float* xr = g_x + (size_t)(rowBase + r) * 6;
        float x0=xr[0], x1=xr[1], x2=xr[2], x3=xr[3], x4=xr[4], x5=xr[5];
#pragma unroll
        for (int c = 0; c < 32; c++) {
            int o = o0 + c;
            float z = b1s[o];
            z = fmaf(w1s[o][0],x0, z); z = fmaf(w1s[o][1],x1, z); z = fmaf(w1s[o][2],x2, z);
            z = fmaf(w1s[o][3],x3, z); z = fmaf(w1s[o][4],x4, z); z = fmaf(w1s[o][5],x5, z);
            a1T[o][r] = fmaxf(fmaf(z, sc1[o], sh1[o]), 0.f);
        }
    }
    __syncthreads();

    int tx = tid & 15, ty = tid >> 4;       // tx: 4-col group, ty: 8-row group
    ull acc[4][4];                          // [row-pair][col]
#pragma unroll
    for (int j = 0; j < 4; j++) {
        ull bp = pack2(b2s[tx*4+j], b2s[tx*4+j]);
#pragma unroll
        for (int pi = 0; pi < 4; pi++) acc[pi][j] = bp;
    }

#pragma unroll 8
    for (int k = 0; k < 64; k++) {
        ulonglong2 ap0 = *(const ulonglong2*)&a1T[k][ty*8];
        ulonglong2 ap1 = *(const ulonglong2*)&a1T[k][ty*8 + 4];
        float4 wv = *(const float4*)&w2s[k][tx*4];
        ull wd0 = pack2(wv.x, wv.x), wd1 = pack2(wv.y, wv.y);
        ull wd2 = pack2(wv.z, wv.z), wd3 = pack2(wv.w, wv.w);
        ull ar[4] = {ap0.x, ap0.y, ap1.x, ap1.y};
#pragma unroll
        for (int pi = 0; pi < 4; pi++) {
            acc[pi][0] = fma2(ar[pi], wd0, acc[pi][0]);
            acc[pi][1] = fma2(ar[pi], wd1, acc[pi][1]);
            acc[pi][2] = fma2(ar[pi], wd2, acc[pi][2]);
            acc[pi][3] = fma2(ar[pi], wd3, acc[pi][3]);
        }
    }

    float z[8][4];
#pragma unroll
    for (int pi = 0; pi < 4; pi++)
#pragma unroll
        for (int j = 0; j < 4; j++) unpack2(acc[pi][j], z[2*pi][j], z[2*pi+1][j]);

    float cs[4] = {0,0,0,0}, cq[4] = {0,0,0,0};
#pragma unroll
    for (int rr = 0; rr < 8; rr++) {
        float4 v = make_float4(z[rr][0], z[rr][1], z[rr][2], z[rr][3]);
        *(float4*)&g_z2[(size_t)(rowBase + ty*8 + rr) * 64 + tx*4] = v;
        cs[0]+=v.x; cs[1]+=v.y; cs[2]+=v.z; cs[3]+=v.w;
        cq[0]=fmaf(v.x,v.x,cq[0]); cq[1]=fmaf(v.y,v.y,cq[1]);
        cq[2]=fmaf(v.z,v.z,cq[2]); cq[3]=fmaf(v.w,v.w,cq[3]);
    }
#pragma unroll
    for (int j = 0; j < 4; j++) { psum[ty][tx*4+j] = cs[j]; psq[ty][tx*4+j] = cq[j]; }
    __syncthreads();
    if (tid < 64) {
        float s = 0.f, s2 = 0.f;
#pragma unroll
        for (int y = 0; y < 8; y++) { s += psum[y][tid]; s2 += psq[y][tid]; }
        atomicAdd(&g_sum2[tid], s);
        atomicAdd(&g_sumsq2[tid], s2);
    }
}

__global__ void params2_kernel(const float* __restrict__ g2, const float* __restrict__ be2) {
    int t = threadIdx.x;
    if (t < 64) {
        float m = g_sum2[t] * NINV;
        float var = g_sumsq2[t] * NINV - m*m;
        float sc = g2[t] * rsqrtf(var + 1e-5f);
        g_scale2[t] = sc; g_shift2[t] = be2[t] - m * sc;
    }
}

// ---------------- pass C: layer3 GEMM (f32x2) + z3 stats + per-group max/min (no z3 store) ----------------
__global__ __launch_bounds__(128) void passC_kernel(const float* __restrict__ w3, const float* __restrict__ b3) {
    __shared__ __align__(16) float a2T[64][72];   // [k][row]
    __shared__ __align__(16) float w3s[64][64];   // [k][o-in-half]
    __shared__ float sc2[64], sh2[64], b3s[64];
    __shared__ float psum[8][64], psq[8][64], pmax[8][64], pmin[8][64];
    int tid = threadIdx.x;
    int colBase = blockIdx.y * 64;

    for (int i = tid; i < 4096; i += 128) {
        int o = i >> 6, c = i & 63;
        w3s[c][o] = w3[(size_t)colBase * 64 + i];   // = w3[(colBase+o)*64 + c], contiguous read
    }
    if (tid < 64) { sc2[tid] = g_scale2[tid]; sh2[tid] = g_shift2[tid]; b3s[tid] = b3[colBase + tid]; }
    __syncthreads();

    int rowBase = blockIdx.x * 64;
    {   // stage 1: a2T[o][r] = relu(affine2(z2)), transposed store
        int r = tid >> 1, o0 = (tid & 1) * 32;
        const float* zr = g_z2 + (size_t)(rowBase + r) * 64 + o0;
#pragma unroll
        for (int q = 0; q < 8; q++) {
            float4 v = *(const float4*)&zr[q*4];
            int o = o0 + q*4;
            a2T[o  ][r] = fmaxf(fmaf(v.x, sc2[o  ], sh2[o  ]), 0.f);
            a2T[o+1][r] = fmaxf(fmaf(v.y, sc2[o+1], sh2[o+1]), 0.f);
            a2T[o+2][r] = fmaxf(fmaf(v.z, sc2[o+2], sh2[o+2]), 0.f);
            a2T[o+3][r] = fmaxf(fmaf(v.w, sc2[o+3], sh2[o+3]), 0.f);
        }
    }
    __syncthreads();

    int tx = tid & 15, ty = tid >> 4;
    ull acc[4][4];
#pragma unroll
    for (int j = 0; j < 4; j++) {
        ull bp = pack2(b3s[tx*4+j], b3s[tx*4+j]);
#pragma unroll
        for (int pi = 0; pi < 4; pi++) acc[pi][j] = bp;
    }

#pragma unroll 8
    for (int k = 0; k < 64; k++) {
        ulonglong2 ap0 = *(const ulonglong2*)&a2T[k][ty*8];
        ulonglong2 ap1 = *(const ulonglong2*)&a2T[k][ty*8 + 4];
        float4 wv = *(const float4*)&w3s[k][tx*4];
        ull wd0 = pack2(wv.x, wv.x), wd1 = pack2(wv.y, wv.y);
        ull wd2 = pack2(wv.z, wv.z), wd3 = pack2(wv.w, wv.w);
        ull ar[4] = {ap0.x, ap0.y, ap1.x, ap1.y};
#pragma unroll
        for (int pi = 0; pi < 4; pi++) {
            acc[pi][0] = fma2(ar[pi], wd0, acc[pi][0]);
            acc[pi][1] = fma2(ar[pi], wd1, acc[pi][1]);
            acc[pi][2] = fma2(ar[pi], wd2, acc[pi][2]);
            acc[pi][3] = fma2(ar[pi], wd3, acc[pi][3]);
        }
    }

    float z[8][4];
#pragma unroll
    for (int pi = 0; pi < 4; pi++)
#pragma unroll
        for (int j = 0; j < 4; j++) unpack2(acc[pi][j], z[2*pi][j], z[2*pi+1][j]);

    float cs[4] = {0,0,0,0}, cq[4] = {0,0,0,0};
    float mx[4] = {-1e30f,-1e30f,-1e30f,-1e30f}, mn[4] = {1e30f,1e30f,1e30f,1e30f};
#pragma unroll
    for (int rr = 0; rr < 8; rr++) {
#pragma unroll
        for (int j = 0; j < 4; j++) {
            float v = z[rr][j];
            cs[j] += v; cq[j] = fmaf(v, v, cq[j]);
            mx[j] = fmaxf(mx[j], v); mn[j] = fminf(mn[j], v);
        }
    }
#pragma unroll
    for (int j = 0; j < 4; j++) {
        psum[ty][tx*4+j] = cs[j]; psq[ty][tx*4+j] = cq[j];
        pmax[ty][tx*4+j] = mx[j]; pmin[ty][tx*4+j] = mn[j];
    }
    __syncthreads();
    if (tid < 64) {
        float s = 0.f, s2 = 0.f;
#pragma unroll
        for (int y = 0; y < 8; y++) { s += psum[y][tid]; s2 += psq[y][tid]; }
        atomicAdd(&g_sum3[colBase + tid], s);
        atomicAdd(&g_sumsq3[colBase + tid], s2);
    }
    {   // per-32-row-group max/min: group 0 = ty 0..3, group 1 = ty 4..7
        int g = tid >> 6, c = tid & 63;
        float M = -1e30f, m = 1e30f;
#pragma unroll
        for (int y = 0; y < 4; y++) {
            M = fmaxf(M, pmax[g*4 + y][c]);
            m = fminf(m, pmin[g*4 + y][c]);
        }
        int gid = blockIdx.x * 2 + g;
        g_max3[(size_t)gid * 128 + colBase + c] = M;
        g_min3[(size_t)gid * 128 + colBase + c] = m;
    }
}

__global__ void params3_kernel(const float* __restrict__ g3, const float* __restrict__ be3) {
    int t = threadIdx.x;
    if (t < 128) {
        float m = g_sum3[t] * NINV;
        float var = g_sumsq3[t] * NINV - m*m;
        float sc = g3[t] * rsqrtf(var + 1e-5f);
        g_scale3[t] = sc; g_shift3[t] = be3[t] - m * sc;
    }
}

// ---------------- pass D: affine3 on pre-reduced max/min + relu ----------------
__global__ __launch_bounds__(256) void passD_kernel(float* __restrict__ out_pts) {
    int idx = blockIdx.x * 256 + threadIdx.x;   // gid*128 + c, 2M total
    int c = idx & 127;
    float sc = g_scale3[c], sh = g_shift3[c];
    float v = (sc >= 0.f) ? g_max3[idx] : g_min3[idx];
    out_pts[idx] = fmaxf(fmaf(v, sc, sh), 0.f);
}

// ---------------- launch ----------------
extern "C" void kernel_launch(void* const* d_in, const int* in_sizes, int n_in,
                              void* d_out, int out_size) {
    const float* xyz = (const float*)d_in[0];
    const float* pts = (const float*)d_in[1];
    const float* w1  = (const float*)d_in[2];
    const float* b1  = (const float*)d_in[3];
    const float* g1  = (const float*)d_in[4];
    const float* be1 = (const float*)d_in[5];
    const float* w2  = (const float*)d_in[6];
    const float* b2  = (const float*)d_in[7];
    const float* g2  = (const float*)d_in[8];
    const float* be2 = (const float*)d_in[9];
    const float* w3  = (const float*)d_in[10];
    const float* b3  = (const float*)d_in[11];
    const float* g3  = (const float*)d_in[12];
    const float* be3 = (const float*)d_in[13];

    float* out      = (float*)d_out;
    float* new_xyz  = out;                 // 16*1024*3 = 49152 floats
    float* new_pts  = out + 49152;         // 16*1024*128 floats

    zero_kernel<<<1, 256>>>();
    prep_kernel<<<512, 256>>>(xyz, pts);
    fps_kernel<<<BB, 512>>>(xyz, new_xyz);
    ball_kernel<<<2048, 256>>>(new_xyz);
    passA_kernel<<<256, 256>>>(new_xyz);
    params1_kernel<<<1, 64>>>(w1, b1, g1, be1);
    passB_kernel<<<8192, 128>>>(w1, b1, w2, b2);
    params2_kernel<<<1, 64>>>(g2, be2);
    passC_kernel<<<dim3(8192, 2), 128>>>(w3, b3);
    params3_kernel<<<1, 128>>>(g3, be3);
    passD_kernel<<<8192, 256>>>(new_pts);
}

// round 5
// speedup vs baseline: 1.3708x; 1.2216x over previous
#include <cuda_runtime.h>

#define BB 16
#define NN 8192
#define SS 1024
#define KK 32
#define NROWS (BB*SS*KK)        // 524288
#define NINV  (1.0f/524288.0f)  // exact power of two
#define R2 0.04f

typedef unsigned long long ull;

// ---------------- f32x2 packed helpers (Blackwell) ----------------
__device__ __forceinline__ ull pack2(float lo, float hi) {
    ull r;
    asm("mov.b64 %0, {%1, %2};" : "=l"(r) : "r"(__float_as_uint(lo)), "r"(__float_as_uint(hi)));
    return r;
}
__device__ __forceinline__ void unpack2(ull v, float& lo, float& hi) {
    unsigned a, b;
    asm("mov.b64 {%0, %1}, %2;" : "=r"(a), "=r"(b) : "l"(v));
    lo = __uint_as_float(a); hi = __uint_as_float(b);
}
__device__ __forceinline__ ull add2(ull a, ull b) {
    ull d; asm("add.rn.f32x2 %0, %1, %2;" : "=l"(d) : "l"(a), "l"(b)); return d;
}
__device__ __forceinline__ ull mul2(ull a, ull b) {
    ull d; asm("mul.rn.f32x2 %0, %1, %2;" : "=l"(d) : "l"(a), "l"(b)); return d;
}
__device__ __forceinline__ ull fma2(ull a, ull b, ull c) {
    ull d; asm("fma.rn.f32x2 %0, %1, %2, %3;" : "=l"(d) : "l"(a), "l"(b), "l"(c)); return d;
}
__device__ __forceinline__ unsigned redux_max_u32(unsigned v) {
    unsigned r;
    asm("redux.sync.max.u32 %0, %1, 0xffffffff;" : "=r"(r) : "r"(v));
    return r;
}

// ---------------- scratch (device globals: no allocation allowed) ----------------
__device__ int    g_ball[NROWS];
__device__ float4 g_xyzp[BB*NN];
__device__ float4 g_pts4[BB*NN];
__device__ float  g_x[(size_t)NROWS*6];
__device__ float  g_z2[(size_t)NROWS*64];
__device__ float  g_max3[BB*SS*128];
__device__ float  g_min3[BB*SS*128];
__device__ float  g_stats0[27];
__device__ float  g_sum2[64],  g_sumsq2[64];
__device__ float  g_sum3[128], g_sumsq3[128];
__device__ float  g_scale1[64], g_shift1[64];
__device__ float  g_scale2[64], g_shift2[64];
__device__ float  g_scale3[128], g_shift3[128];

// ---------------- zero stats (graph replays must re-zero) ----------------
__global__ void zero_kernel() {
    int t = threadIdx.x;
    if (t < 27)  g_stats0[t] = 0.f;
    if (t < 64)  { g_sum2[t] = 0.f; g_sumsq2[t] = 0.f; }
    if (t < 128) { g_sum3[t] = 0.f; g_sumsq3[t] = 0.f; }
}

// ---------------- FPS: one block per batch, 256 thr x 32 pts (reg-budget safe) ----------
// Also performs "prep" (g_xyzp / g_pts4 packing) for its batch during init.
__global__ __launch_bounds__(256) void fps_kernel(const float* __restrict__ xyz,
                                                  const float* __restrict__ pts,
                                                  float* __restrict__ new_xyz) {
    const int b = blockIdx.x;
    const float* base  = xyz + (size_t)b * NN * 3;
    const float* pbase = pts + (size_t)b * NN * 3;
    const int t = threadIdx.x;

    ull px2[16], py2[16], pz2[16];
    float dist[32];
#pragma unroll
    for (int p = 0; p < 16; p++) {
        int i0 = (2*p)*256 + t, i1 = i0 + 256;
        float x0 = base[3*i0], y0 = base[3*i0+1], z0 = base[3*i0+2];
        float x1 = base[3*i1], y1 = base[3*i1+1], z1 = base[3*i1+2];
        px2[p] = pack2(x0, x1); py2[p] = pack2(y0, y1); pz2[p] = pack2(z0, z1);
        g_xyzp[b*NN + i0] = make_float4(x0, y0, z0, fmaf(x0,x0,fmaf(y0,y0,z0*z0)));
        g_xyzp[b*NN + i1] = make_float4(x1, y1, z1, fmaf(x1,x1,fmaf(y1,y1,z1*z1)));
        g_pts4[b*NN + i0] = make_float4(pbase[3*i0], pbase[3*i0+1], pbase[3*i0+2], 0.f);
        g_pts4[b*NN + i1] = make_float4(pbase[3*i1], pbase[3*i1+1], pbase[3*i1+2], 0.f);
        dist[2*p] = 1e10f; dist[2*p+1] = 1e10f;
    }

    __shared__ float    s_c[3];
    __shared__ unsigned s_M;
    __shared__ int      s_idx;
    if (t == 0) { s_c[0]=base[0]; s_c[1]=base[1]; s_c[2]=base[2]; s_M=0u; s_idx=0x7fffffff; }
    __syncthreads();

    float* out = new_xyz + (size_t)b * SS * 3;
    const int lane = t & 31;
    for (int it = 0; it < SS; it++) {
        float cx = s_c[0], cy = s_c[1], cz = s_c[2];
        if (t == 0) { out[3*it] = cx; out[3*it+1] = cy; out[3*it+2] = cz; }
        ull nx2 = pack2(-cx,-cx), ny2 = pack2(-cy,-cy), nz2 = pack2(-cz,-cz);

        // compute: d = (x-cx)^2+(y-cy)^2+(z-cz)^2 (bit-identical to reference form),
        // dist = min(dist,d), track max value only (4-way tree to shorten dep chain)
        float bv0 = 0.f, bv1 = 0.f, bv2 = 0.f, bv3 = 0.f;
#pragma unroll
        for (int p = 0; p < 16; p++) {
            ull dx = add2(px2[p], nx2);
            ull dy = add2(py2[p], ny2);
            ull dz = add2(pz2[p], nz2);
            ull d2 = fma2(dx, dx, fma2(dy, dy, mul2(dz, dz)));
            float d0, d1; unpack2(d2, d0, d1);
            float n0 = fminf(dist[2*p], d0);   dist[2*p]   = n0;
            float n1 = fminf(dist[2*p+1], d1); dist[2*p+1] = n1;
            if (p & 1) { bv1 = fmaxf(bv1, n0); bv3 = fmaxf(bv3, n1); }
            else       { bv0 = fmaxf(bv0, n0); bv2 = fmaxf(bv2, n1); }
        }
        float bv = fmaxf(fmaxf(bv0, bv1), fmaxf(bv2, bv3));
        // all dists >= 0 -> float bits are monotone under u32 compare
        unsigned mb   = __float_as_uint(bv);
        unsigned wmax = redux_max_u32(mb);
        if (lane == 0) atomicMax(&s_M, wmax);
        __syncthreads();

        unsigned M = s_M;
        if (mb == M) {   // only the winning warp(s) pay for the index search
            int cand = 0x7fffffff;
#pragma unroll
            for (int j = 31; j >= 0; j--)
                if (__float_as_uint(dist[j]) == M) cand = j*256 + t;  // lowest j wins
            atomicMin(&s_idx, cand);     // lowest global index wins (argmax 1st-occurrence)
        }
        __syncthreads();

        if (t == 0) {
            int i2 = s_idx;
            s_c[0] = base[3*i2]; s_c[1] = base[3*i2+1]; s_c[2] = base[3*i2+2];
            s_M = 0u; s_idx = 0x7fffffff;
        }
        __syncthreads();
    }
}

// ---------------- ball query: one warp per centroid, pipelined (MLP=4) ----------------
__global__ __launch_bounds__(256) void ball_kernel(const float* __restrict__ new_xyz) {
    int w    = (blockIdx.x * 256 + threadIdx.x) >> 5;  // global centroid id (b*S+s)
    int lane = threadIdx.x & 31;
    int b    = w >> 10;
    const float4* xp = g_xyzp + b * NN;
    float cx = new_xyz[3*w], cy = new_xyz[3*w+1], cz = new_xyz[3*w+2];
    float ss = fmaf(cx,cx, fmaf(cy,cy, cz*cz));
    int* outp = g_ball + w * KK;

    int count = 0, first = 0;
    for (int base = 0; base < NN && count < KK; base += 128) {
        float4 p0 = xp[base      + lane];
        float4 p1 = xp[base + 32 + lane];
        float4 p2 = xp[base + 64 + lane];
        float4 p3 = xp[base + 96 + lane];
#define BQ_STEP(P, OFF) { \
        float dot = fmaf(cx,(P).x, fmaf(cy,(P).y, cz*(P).z)); \
        float sq  = fmaf(-2.f, dot, ss) + (P).w; \
        bool hit  = !(sq > R2); \
        unsigned m = __ballot_sync(0xffffffffu, hit); \
        if (count == 0 && m) first = base + (OFF) + __ffs(m) - 1; \
        int pos = count + __popc(m & ((1u << lane) - 1u)); \
        if (hit && pos < KK) outp[pos] = base + (OFF) + lane; \
        count += __popc(m); }
        BQ_STEP(p0, 0) BQ_STEP(p1, 32) BQ_STEP(p2, 64) BQ_STEP(p3, 96)
#undef BQ_STEP
    }
    if (count < KK && lane >= count && lane < KK) outp[lane] = first;
}

// ---------------- pass A: gather features, store x, accumulate 6-vec mean + 21 Gram ----------------
__global__ __launch_bounds__(256) void passA_kernel(const float* __restrict__ new_xyz) {
    int gt = blockIdx.x * 256 + threadIdx.x;   // 65536 threads, 8 rows each
    float acc[27];
#pragma unroll
    for (int q = 0; q < 27; q++) acc[q] = 0.f;

    for (int i = 0; i < 8; i++) {
        int row = i * 65536 + gt;
        int idx = g_ball[row];
        int b   = row >> 15;
        int bs  = row >> 5;
        float4 p = g_xyzp[b*NN + idx];
        float4 q = g_pts4[b*NN + idx];
        float f[6];
        f[0] = p.x - new_xyz[3*bs];
        f[1] = p.y - new_xyz[3*bs+1];
        f[2] = p.z - new_xyz[3*bs+2];
        f[3] = q.x; f[4] = q.y; f[5] = q.z;
        float* xr = g_x + (size_t)row * 6;
#pragma unroll
        for (int c = 0; c < 6; c++) xr[c] = f[c];
#pragma unroll
        for (int c = 0; c < 6; c++) acc[c] += f[c];
        int pidx = 6;
#pragma unroll
        for (int a = 0; a < 6; a++)
#pragma unroll
            for (int c = a; c < 6; c++) acc[pidx++] = fmaf(f[a], f[c], acc[pidx]);
    }
#pragma unroll
    for (int q = 0; q < 27; q++) {
        float v = acc[q];
#pragma unroll
        for (int o = 16; o > 0; o >>= 1) v += __shfl_down_sync(0xffffffffu, v, o);
        if ((threadIdx.x & 31) == 0) atomicAdd(&g_stats0[q], v);
    }
}

// ---------------- params1: layer-1 BN stats from Gram ----------------
__global__ void params1_kernel(const float* __restrict__ w1, const float* __restrict__ b1,
                               const float* __restrict__ g1, const float* __restrict__ be1) {
    __shared__ float mu[6], C2[6][6];
    int t = threadIdx.x;
    if (t < 6) mu[t] = g_stats0[t] * NINV;
    if (t < 36) {
        int i = t / 6, j = t % 6;
        int a = i < j ? i : j, c = i < j ? j : i;
        int pos = 6 + 6*a - (a*(a-1))/2 + (c - a);
        C2[i][j] = g_stats0[pos] * NINV;
    }
    __syncthreads();
    if (t < 64) {
        float lin = 0.f;
#pragma unroll
        for (int c = 0; c < 6; c++) lin += w1[t*6+c] * mu[c];
        float m = lin + b1[t];
        float qv = 0.f;
#pragma unroll
        for (int i = 0; i < 6; i++)
#pragma unroll
            for (int j = 0; j < 6; j++) qv += w1[t*6+i] * w1[t*6+j] * C2[i][j];
        float Ez2 = qv + 2.f * b1[t] * lin + b1[t]*b1[t];
        float var = Ez2 - m*m;
        float sc  = g1[t] * rsqrtf(var + 1e-5f);
        g_scale1[t] = sc;
        g_shift1[t] = be1[t] - m * sc;
    }
}

// ---------------- pass B: layer1 (affine-folded) + layer2 GEMM (f32x2) + z2 stats ----------------
__global__ __launch_bounds__(128) void passB_kernel(const float* __restrict__ w1, const float* __restrict__ b1,
                                                    const float* __restrict__ w2, const float* __restrict__ b2) {
    __shared__ __align__(16) float a1T[64][72];   // [k][row]
    __shared__ __align__(16) float w2s[64][64];   // [k][o]
    __shared__ float w1s[64][6], b1s[64], sc1[64], sh1[64], b2s[64];
    __shared__ float psum[8][64], psq[8][64];
    int tid = threadIdx.x;

    for (int i = tid; i < 4096; i += 128) { int o = i >> 6, c = i & 63; w2s[c][o] = w2[i]; }
    for (int i = tid; i < 384; i += 128) w1s[i/6][i%6] = w1[i];
    if (tid < 64) { b1s[tid] = b1[tid]; sc1[tid] = g_scale1[tid]; sh1[tid] = g_shift1[tid]; b2s[tid] = b2[tid]; }
    __syncthreads();

    int rowBase = blockIdx.x * 64;
    {   // stage 1: a1T[o][r] = relu(affine1(W1 x + b1)), transposed store
        int r = tid >> 1, o0 = (tid & 1) * 32;
        const float* xr = g_x + (size_t)(rowBase + r) * 6;
        float x0=xr[0], x1=xr[1], x2=xr[2], x3=xr[3], x4=xr[4], x5=xr[5];
#pragma unroll
        for (int c = 0; c < 32; c++) {
            int o = o0 + c;
            float z = b1s[o];
            z = fmaf(w1s[o][0],x0, z); z = fmaf(w1s[o][1],x1, z); z = fmaf(w1s[o][2],x2, z);
            z = fmaf(w1s[o][3],x3, z); z = fmaf(w1s[o][4],x4, z); z = fmaf(w1s[o][5],x5, z);
            a1T[o][r] = fmaxf(fmaf(z, sc1[o], sh1[o]), 0.f);
        }
    }
    __syncthreads();

    int tx = tid & 15, ty = tid >> 4;       // tx: 4-col group, ty: 8-row group
    ull acc[4][4];                          // [row-pair][col]
#pragma unroll
    for (int j = 0; j < 4; j++) {
        ull bp = pack2(b2s[tx*4+j], b2s[tx*4+j]);
#pragma unroll
        for (int pi = 0; pi < 4; pi++) acc[pi][j] = bp;
    }

#pragma unroll 8
    for (int k = 0; k < 64; k++) {
        ulonglong2 ap0 = *(const ulonglong2*)&a1T[k][ty*8];
        ulonglong2 ap1 = *(const ulonglong2*)&a1T[k][ty*8 + 4];
        float4 wv = *(const float4*)&w2s[k][tx*4];
        ull wd0 = pack2(wv.x, wv.x), wd1 = pack2(wv.y, wv.y);
        ull wd2 = pack2(wv.z, wv.z), wd3 = pack2(wv.w, wv.w);
        ull ar[4] = {ap0.x, ap0.y, ap1.x, ap1.y};
#pragma unroll
        for (int pi = 0; pi < 4; pi++) {
            acc[pi][0] = fma2(ar[pi], wd0, acc[pi][0]);
            acc[pi][1] = fma2(ar[pi], wd1, acc[pi][1]);
            acc[pi][2] = fma2(ar[pi], wd2, acc[pi][2]);
            acc[pi][3] = fma2(ar[pi], wd3, acc[pi][3]);
        }
    }

    float z[8][4];
#pragma unroll
    for (int pi = 0; pi < 4; pi++)
#pragma unroll
        for (int j = 0; j < 4; j++) unpack2(acc[pi][j], z[2*pi][j], z[2*pi+1][j]);

    float cs[4] = {0,0,0,0}, cq[4] = {0,0,0,0};
#pragma unroll
    for (int rr = 0; rr < 8; rr++) {
        float4 v = make_float4(z[rr][0], z[rr][1], z[rr][2], z[rr][3]);
        *(float4*)&g_z2[(size_t)(rowBase + ty*8 + rr) * 64 + tx*4] = v;
        cs[0]+=v.x; cs[1]+=v.y; cs[2]+=v.z; cs[3]+=v.w;
        cq[0]=fmaf(v.x,v.x,cq[0]); cq[1]=fmaf(v.y,v.y,cq[1]);
        cq[2]=fmaf(v.z,v.z,cq[2]); cq[3]=fmaf(v.w,v.w,cq[3]);
    }
#pragma unroll
    for (int j = 0; j < 4; j++) { psum[ty][tx*4+j] = cs[j]; psq[ty][tx*4+j] = cq[j]; }
    __syncthreads();
    if (tid < 64) {
        float s = 0.f, s2 = 0.f;
#pragma unroll
        for (int y = 0; y < 8; y++) { s += psum[y][tid]; s2 += psq[y][tid]; }
        atomicAdd(&g_sum2[tid], s);
        atomicAdd(&g_sumsq2[tid], s2);
    }
}

__global__ void params2_kernel(const float* __restrict__ g2, const float* __restrict__ be2) {
    int t = threadIdx.x;
    if (t < 64) {
        float m = g_sum2[t] * NINV;
        float var = g_sumsq2[t] * NINV - m*m;
        float sc = g2[t] * rsqrtf(var + 1e-5f);
        g_scale2[t] = sc; g_shift2[t] = be2[t] - m * sc;
    }
}

// ---------------- pass C: layer3 GEMM (f32x2) + z3 stats + per-group max/min (no z3 store) ----------------
__global__ __launch_bounds__(128) void passC_kernel(const float* __restrict__ w3, const float* __restrict__ b3) {
    __shared__ __align__(16) float a2T[64][72];   // [k][row]
    __shared__ __align__(16) float w3s[64][64];   // [k][o-in-half]
    __shared__ float sc2[64], sh2[64], b3s[64];
    __shared__ float psum[8][64], psq[8][64], pmax[8][64], pmin[8][64];
    int tid = threadIdx.x;
    int colBase = blockIdx.y * 64;

    for (int i = tid; i < 4096; i += 128) {
        int o = i >> 6, c = i & 63;
        w3s[c][o] = w3[(size_t)colBase * 64 + i];   // = w3[(colBase+o)*64 + c], contiguous read
    }
    if (tid < 64) { sc2[tid] = g_scale2[tid]; sh2[tid] = g_shift2[tid]; b3s[tid] = b3[colBase + tid]; }
    __syncthreads();

    int rowBase = blockIdx.x * 64;
    {   // stage 1: a2T[o][r] = relu(affine2(z2)), transposed store
        int r = tid >> 1, o0 = (tid & 1) * 32;
        const float* zr = g_z2 + (size_t)(rowBase + r) * 64 + o0;
#pragma unroll
        for (int q = 0; q < 8; q++) {
            float4 v = *(const float4*)&zr[q*4];
            int o = o0 + q*4;
            a2T[o  ][r] = fmaxf(fmaf(v.x, sc2[o  ], sh2[o  ]), 0.f);
            a2T[o+1][r] = fmaxf(fmaf(v.y, sc2[o+1], sh2[o+1]), 0.f);
            a2T[o+2][r] = fmaxf(fmaf(v.z, sc2[o+2], sh2[o+2]), 0.f);
            a2T[o+3][r] = fmaxf(fmaf(v.w, sc2[o+3], sh2[o+3]), 0.f);
        }
    }
    __syncthreads();

    int tx = tid & 15, ty = tid >> 4;
    ull acc[4][4];
#pragma unroll
    for (int j = 0; j < 4; j++) {
        ull bp = pack2(b3s[tx*4+j], b3s[tx*4+j]);
#pragma unroll
        for (int pi = 0; pi < 4; pi++) acc[pi][j] = bp;
    }

#pragma unroll 8
    for (int k = 0; k < 64; k++) {
        ulonglong2 ap0 = *(const ulonglong2*)&a2T[k][ty*8];
        ulonglong2 ap1 = *(const ulonglong2*)&a2T[k][ty*8 + 4];
        float4 wv = *(const float4*)&w3s[k][tx*4];
        ull wd0 = pack2(wv.x, wv.x), wd1 = pack2(wv.y, wv.y);
        ull wd2 = pack2(wv.z, wv.z), wd3 = pack2(wv.w, wv.w);
        ull ar[4] = {ap0.x, ap0.y, ap1.x, ap1.y};
#pragma unroll
        for (int pi = 0; pi < 4; pi++) {
            acc[pi][0] = fma2(ar[pi], wd0, acc[pi][0]);
            acc[pi][1] = fma2(ar[pi], wd1, acc[pi][1]);
            acc[pi][2] = fma2(ar[pi], wd2, acc[pi][2]);
            acc[pi][3] = fma2(ar[pi], wd3, acc[pi][3]);
        }
    }

    float z[8][4];
#pragma unroll
    for (int pi = 0; pi < 4; pi++)
#pragma unroll
        for (int j = 0; j < 4; j++) unpack2(acc[pi][j], z[2*pi][j], z[2*pi+1][j]);

    float cs[4] = {0,0,0,0}, cq[4] = {0,0,0,0};
    float mx[4] = {-1e30f,-1e30f,-1e30f,-1e30f}, mn[4] = {1e30f,1e30f,1e30f,1e30f};
#pragma unroll
    for (int rr = 0; rr < 8; rr++) {
#pragma unroll
        for (int j = 0; j < 4; j++) {
            float v = z[rr][j];
            cs[j] += v; cq[j] = fmaf(v, v, cq[j]);
            mx[j] = fmaxf(mx[j], v); mn[j] = fminf(mn[j], v);
        }
    }
#pragma unroll
    for (int j = 0; j < 4; j++) {
        psum[ty][tx*4+j] = cs[j]; psq[ty][tx*4+j] = cq[j];
        pmax[ty][tx*4+j] = mx[j]; pmin[ty][tx*4+j] = mn[j];
    }
    __syncthreads();
    if (tid < 64) {
        float s = 0.f, s2 = 0.f;
#pragma unroll
        for (int y = 0; y < 8; y++) { s += psum[y][tid]; s2 += psq[y][tid]; }
        atomicAdd(&g_sum3[colBase + tid], s);
        atomicAdd(&g_sumsq3[colBase + tid], s2);
    }
    {   // per-32-row-group max/min: group 0 = ty 0..3, group 1 = ty 4..7
        int g = tid >> 6, c = tid & 63;
        float M = -1e30f, m = 1e30f;
#pragma unroll
        for (int y = 0; y < 4; y++) {
            M = fmaxf(M, pmax[g*4 + y][c]);
            m = fminf(m, pmin[g*4 + y][c]);
        }
        int gid = blockIdx.x * 2 + g;
        g_max3[(size_t)gid * 128 + colBase + c] = M;
        g_min3[(size_t)gid * 128 + colBase + c] = m;
    }
}

__global__ void params3_kernel(const float* __restrict__ g3, const float* __restrict__ be3) {
    int t = threadIdx.x;
    if (t < 128) {
        float m = g_sum3[t] * NINV;
        float var = g_sumsq3[t] * NINV - m*m;
        float sc = g3[t] * rsqrtf(var + 1e-5f);
        g_scale3[t] = sc; g_shift3[t] = be3[t] - m * sc;
    }
}

// ---------------- pass D: affine3 on pre-reduced max/min + relu ----------------
__global__ __launch_bounds__(256) void passD_kernel(float* __restrict__ out_pts) {
    int idx = blockIdx.x * 256 + threadIdx.x;   // gid*128 + c, 2M total
    int c = idx & 127;
    float sc = g_scale3[c], sh = g_shift3[c];
    float v = (sc >= 0.f) ? g_max3[idx] : g_min3[idx];
    out_pts[idx] = fmaxf(fmaf(v, sc, sh), 0.f);
}

// ---------------- launch ----------------
extern "C" void kernel_launch(void* const* d_in, const int* in_sizes, int n_in,
                              void* d_out, int out_size) {
    const float* xyz = (const float*)d_in[0];
    const float* pts = (const float*)d_in[1];
    const float* w1  = (const float*)d_in[2];
    const float* b1  = (const float*)d_in[3];
    const float* g1  = (const float*)d_in[4];
    const float* be1 = (const float*)d_in[5];
    const float* w2  = (const float*)d_in[6];
    const float* b2  = (const float*)d_in[7];
    const float* g2  = (const float*)d_in[8];
    const float* be2 = (const float*)d_in[9];
    const float* w3  = (const float*)d_in[10];
    const float* b3  = (const float*)d_in[11];
    const float* g3  = (const float*)d_in[12];
    const float* be3 = (const float*)d_in[13];

    float* out      = (float*)d_out;
    float* new_xyz  = out;                 // 16*1024*3 = 49152 floats
    float* new_pts  = out + 49152;         // 16*1024*128 floats

    zero_kernel<<<1, 256>>>();
    fps_kernel<<<BB, 256>>>(xyz, pts, new_xyz);
    ball_kernel<<<2048, 256>>>(new_xyz);
    passA_kernel<<<256, 256>>>(new_xyz);
    params1_kernel<<<1, 64>>>(w1, b1, g1, be1);
    passB_kernel<<<8192, 128>>>(w1, b1, w2, b2);
    params2_kernel<<<1, 64>>>(g2, be2);
    passC_kernel<<<dim3(8192, 2), 128>>>(w3, b3);
    params3_kernel<<<1, 128>>>(g3, be3);
    passD_kernel<<<8192, 256>>>(new_pts);
}